// round 10
// baseline (speedup 1.0000x reference)
#include <cuda_runtime.h>
#include <cstdint>

// out[64,14336] = x[64,4096] @ dequant(W_int) + bias + x.sum(-1)*u
// tf32 mma.sync; cp.async 4-stage ring; W raw int32 in smem -> I2F only
// (exact in tf32); scales folded per-group into fp32 accumulators with
// D-fragment column indexing (col = 2*(lane&3)+{0,1}).
// x pre-rounded to tf32 and k-pair-interleaved by prep kernel (A frags = LDS.64).

#define TOKS   64
#define INF    4096
#define OUTF   14336
#define KC     64
#define NCHUNK (INF / KC)      // 64
#define NTILE  128
#define NCTA   (OUTF / NTILE)  // 112
#define STAGES 4

// smem strides (words): W stride % 32 == 8 -> 136 (LDS.32 frags conflict-free)
//                       x stride % 32 == 8 -> 72  (LDS.64 pair frags conflict-free)
#define WSTR 136
#define XSTR 72
#define W_STAGE_WORDS (KC * WSTR)            // 8704
#define X_STAGE_WORDS (TOKS * XSTR)          // 4608
#define STAGE_WORDS   (W_STAGE_WORDS + X_STAGE_WORDS)   // 13312
#define STAGE_BYTES   (STAGE_WORDS * 4)                 // 53248
#define W_STAGE_BYTES (W_STAGE_WORDS * 4)               // 34816
#define SMEM_BYTES    (STAGES * STAGE_BYTES)            // 212992

__device__ float g_xtf[TOKS * INF];   // tf32-rounded x, k-interleaved pairs
__device__ float g_xsum[TOKS];

static __device__ __forceinline__ uint32_t f2tf(float f) {
    uint32_t r;
    asm("cvt.rna.tf32.f32 %0, %1;" : "=r"(r) : "f"(f));
    return r;
}
static __device__ __forceinline__ uint32_t smem_u32(const void* p) {
    uint32_t a;
    asm("{ .reg .u64 t; cvta.to.shared.u64 t, %1; cvt.u32.u64 %0, t; }" : "=r"(a) : "l"(p));
    return a;
}
static __device__ __forceinline__ void cpasync16(uint32_t dst, const void* src) {
    asm volatile("cp.async.cg.shared.global [%0], [%1], 16;" :: "r"(dst), "l"(src));
}
static __device__ __forceinline__ void mma8(float* d, const uint32_t* a, const uint32_t* b) {
    asm volatile(
        "mma.sync.aligned.m16n8k8.row.col.f32.tf32.tf32.f32 "
        "{%0,%1,%2,%3}, {%4,%5,%6,%7}, {%8,%9}, {%0,%1,%2,%3};"
        : "+f"(d[0]), "+f"(d[1]), "+f"(d[2]), "+f"(d[3])
        : "r"(a[0]), "r"(a[1]), "r"(a[2]), "r"(a[3]), "r"(b[0]), "r"(b[1]));
}

// ---------- prep: x -> tf32, k-pair-interleave; per-token row sums ----------
// within each 8-block: original j stored at (j&3)*2 + (j>>2)  -> pairs (k,k+4) adjacent
__global__ void __launch_bounds__(256) prep_kernel(const float* __restrict__ x) {
    const int row = blockIdx.x;
    const int t = threadIdx.x;
    const float* xr = x + row * INF;
    float s = 0.f;
    #pragma unroll
    for (int i = 0; i < INF / 256; ++i) {
        const int k = t + i * 256;
        const float v = xr[k];
        s += v;
        const int j = k & 7;
        const int pos = (k & ~7) + ((j & 3) * 2 + (j >> 2));
        g_xtf[row * INF + pos] = __uint_as_float(f2tf(v));
    }
    #pragma unroll
    for (int off = 16; off; off >>= 1) s += __shfl_xor_sync(0xffffffffu, s, off);
    __shared__ float red[8];
    if ((t & 31) == 0) red[t >> 5] = s;
    __syncthreads();
    if (t < 8) {
        float v = red[t];
        #pragma unroll
        for (int off = 4; off; off >>= 1) v += __shfl_xor_sync(0xffu, v, off);
        if (t == 0) g_xsum[row] = v;
    }
}

// ---------- main GEMM ----------
__global__ void __launch_bounds__(256, 1)
qbits_kernel(const int* __restrict__ W, const float* __restrict__ scales,
             const float* __restrict__ u, const float* __restrict__ bias,
             float* __restrict__ out)
{
    extern __shared__ uint32_t smem[];
    const uint32_t sbase = smem_u32(smem);
    const int tid  = threadIdx.x;
    const int lane = tid & 31;
    const int warp = tid >> 5;          // 0..7
    const int wm   = warp >> 2;         // 0..1
    const int wn   = warp & 3;          // 0..3
    const int obase = blockIdx.x * NTILE;

    // copy geometry
    const int*   wsrc = W + obase + (lane << 2);
    const float* xsrc = g_xtf + (tid >> 2) * INF + ((tid & 3) << 4);
    const uint32_t wdst_off = (uint32_t)((warp * WSTR + (lane << 2)) * 4);
    const uint32_t xdst_off = (uint32_t)(W_STAGE_BYTES +
                              (((tid >> 2) * XSTR + ((tid & 3) << 4)) * 4));

    float acc[2][4][4];   // scaled accumulators
    float accg[2][4][4];  // per-group raw accumulators
    #pragma unroll
    for (int mt = 0; mt < 2; ++mt)
        #pragma unroll
        for (int nt = 0; nt < 4; ++nt)
            #pragma unroll
            for (int j = 0; j < 4; ++j) { acc[mt][nt][j] = 0.f; accg[mt][nt][j] = 0.f; }

    auto issue = [&](int c, int s) {
        const int k0 = c * KC;
        const uint32_t wb = sbase + (uint32_t)(s * STAGE_BYTES);
        #pragma unroll
        for (int p = 0; p < 8; ++p)
            cpasync16(wb + wdst_off + (uint32_t)(p * 8 * WSTR * 4),
                      wsrc + (k0 + warp + 8 * p) * OUTF);
        #pragma unroll
        for (int i = 0; i < 4; ++i)
            cpasync16(wb + xdst_off + (uint32_t)(i * 16), xsrc + k0 + i * 4);
        asm volatile("cp.async.commit_group;" ::: "memory");
    };

    #pragma unroll
    for (int s = 0; s < STAGES - 1; ++s) issue(s, s);

    // D-fragment column scales: cols (2*(lane&3), 2*(lane&3)+1) per nt
    float2 sc2[4];
    int st = 0;
    for (int c = 0; c < NCHUNK; ++c) {
        asm volatile("cp.async.wait_group %0;" :: "n"(STAGES - 2) : "memory");
        __syncthreads();
        if (c + STAGES - 1 < NCHUNK) {
            int sn = st + STAGES - 1; if (sn >= STAGES) sn -= STAGES;
            issue(c + STAGES - 1, sn);
        }

        if ((c & 1) == 0) {   // group start: fetch this group's D-column scales
            const float* srow = scales + (c >> 1) * OUTF + obase
                              + wn * 32 + 2 * (lane & 3);
            #pragma unroll
            for (int nt = 0; nt < 4; ++nt)
                sc2[nt] = __ldg((const float2*)(srow + nt * 8));
        }

        const uint32_t* ws  = smem + st * STAGE_WORDS;
        const float*    xsm = (const float*)(ws + W_STAGE_WORDS);

        #pragma unroll
        for (int ks = 0; ks < 8; ++ks) {
            const int kp = ks * 8 + 2 * (lane & 3);   // interleaved pair offset
            const int kk = ks * 8 + (lane & 3);
            uint32_t a[2][4];
            #pragma unroll
            for (int mt = 0; mt < 2; ++mt) {
                const int r = wm * 32 + mt * 16 + (lane >> 2);
                const float2 p0 = *(const float2*)(xsm + r * XSTR + kp);        // (a0,a2)
                const float2 p1 = *(const float2*)(xsm + (r + 8) * XSTR + kp);  // (a1,a3)
                a[mt][0] = __float_as_uint(p0.x);
                a[mt][1] = __float_as_uint(p1.x);
                a[mt][2] = __float_as_uint(p0.y);
                a[mt][3] = __float_as_uint(p1.y);
            }
            #pragma unroll
            for (int nt = 0; nt < 4; ++nt) {
                const int col = wn * 32 + nt * 8 + (lane >> 2);
                const int w0 = (int)ws[kk * WSTR + col];
                const int w1 = (int)ws[(kk + 4) * WSTR + col];
                uint32_t bb[2];
                bb[0] = __float_as_uint((float)w0);   // exact in tf32
                bb[1] = __float_as_uint((float)w1);
                mma8(accg[0][nt], a[0], bb);
                mma8(accg[1][nt], a[1], bb);
            }
        }

        if (c & 1) {          // group end: fold per-D-column scale, reset raw acc
            #pragma unroll
            for (int mt = 0; mt < 2; ++mt)
                #pragma unroll
                for (int nt = 0; nt < 4; ++nt) {
                    acc[mt][nt][0] = fmaf(sc2[nt].x, accg[mt][nt][0], acc[mt][nt][0]);
                    acc[mt][nt][1] = fmaf(sc2[nt].y, accg[mt][nt][1], acc[mt][nt][1]);
                    acc[mt][nt][2] = fmaf(sc2[nt].x, accg[mt][nt][2], acc[mt][nt][2]);
                    acc[mt][nt][3] = fmaf(sc2[nt].y, accg[mt][nt][3], acc[mt][nt][3]);
                    accg[mt][nt][0] = 0.f; accg[mt][nt][1] = 0.f;
                    accg[mt][nt][2] = 0.f; accg[mt][nt][3] = 0.f;
                }
        }
        if (++st == STAGES) st = 0;
    }

    // ---- epilogue: out = acc + bias + xsum*u ----
    #pragma unroll
    for (int mt = 0; mt < 2; ++mt) {
        #pragma unroll
        for (int jr = 0; jr < 2; ++jr) {
            const int row = wm * 32 + mt * 16 + (lane >> 2) + jr * 8;
            const float xsv = g_xsum[row];
            #pragma unroll
            for (int nt = 0; nt < 4; ++nt) {
                const int col = obase + wn * 32 + nt * 8 + 2 * (lane & 3);
                const float2 bv = *(const float2*)(bias + col);
                const float2 uv = *(const float2*)(u + col);
                float2 o2;
                o2.x = acc[mt][nt][jr * 2 + 0] + bv.x + xsv * uv.x;
                o2.y = acc[mt][nt][jr * 2 + 1] + bv.y + xsv * uv.y;
                *(float2*)(out + row * OUTF + col) = o2;
            }
        }
    }
}

extern "C" void kernel_launch(void* const* d_in, const int* in_sizes, int n_in,
                              void* d_out, int out_size) {
    const float* x  = (const float*)d_in[0];
    const int*   W  = (const int*)d_in[1];
    const float* sc = (const float*)d_in[2];
    const float* u  = (const float*)d_in[3];
    const float* b  = (const float*)d_in[4];
    float* out = (float*)d_out;

    cudaFuncSetAttribute(qbits_kernel, cudaFuncAttributeMaxDynamicSharedMemorySize,
                         SMEM_BYTES);
    prep_kernel<<<TOKS, 256>>>(x);
    qbits_kernel<<<NCTA, 256, SMEM_BYTES>>>(W, sc, u, b, out);
}

// round 12
// speedup vs baseline: 1.1448x; 1.1448x over previous
#include <cuda_runtime.h>
#include <cstdint>

// out[64,14336] = x[64,4096] @ dequant(W_int) + bias + x.sum(-1)*u
// tf32 mma.sync; cp.async 4-stage ring; W raw int32 in smem -> I2F (exact in
// tf32); scales folded per-group into fp32 accumulators (D-fragment columns).
// 512 threads / 16 warps (2M x 8N), warp tile m32n16 -> 4 warps/SMSP for
// latency hiding (R10 was issue-starved at 2 warps/SMSP).

#define TOKS   64
#define INF    4096
#define OUTF   14336
#define KC     64
#define NCHUNK (INF / KC)      // 64
#define NTILE  128
#define NCTA   (OUTF / NTILE)  // 112
#define STAGES 4

// smem strides (words): W stride % 32 == 8 -> 136 ; x stride % 32 == 8 -> 72
#define WSTR 136
#define XSTR 72
#define W_STAGE_WORDS (KC * WSTR)            // 8704
#define X_STAGE_WORDS (TOKS * XSTR)          // 4608
#define STAGE_WORDS   (W_STAGE_WORDS + X_STAGE_WORDS)   // 13312
#define STAGE_BYTES   (STAGE_WORDS * 4)                 // 53248
#define W_STAGE_BYTES (W_STAGE_WORDS * 4)               // 34816
#define SMEM_BYTES    (STAGES * STAGE_BYTES)            // 212992

__device__ float g_xtf[TOKS * INF];   // tf32-rounded x, k-pair-interleaved
__device__ float g_xsum[TOKS];

static __device__ __forceinline__ uint32_t f2tf(float f) {
    uint32_t r;
    asm("cvt.rna.tf32.f32 %0, %1;" : "=r"(r) : "f"(f));
    return r;
}
static __device__ __forceinline__ uint32_t smem_u32(const void* p) {
    uint32_t a;
    asm("{ .reg .u64 t; cvta.to.shared.u64 t, %1; cvt.u32.u64 %0, t; }" : "=r"(a) : "l"(p));
    return a;
}
static __device__ __forceinline__ void cpasync16(uint32_t dst, const void* src) {
    asm volatile("cp.async.cg.shared.global [%0], [%1], 16;" :: "r"(dst), "l"(src));
}
static __device__ __forceinline__ void mma8(float* d, const uint32_t* a, const uint32_t* b) {
    asm volatile(
        "mma.sync.aligned.m16n8k8.row.col.f32.tf32.tf32.f32 "
        "{%0,%1,%2,%3}, {%4,%5,%6,%7}, {%8,%9}, {%0,%1,%2,%3};"
        : "+f"(d[0]), "+f"(d[1]), "+f"(d[2]), "+f"(d[3])
        : "r"(a[0]), "r"(a[1]), "r"(a[2]), "r"(a[3]), "r"(b[0]), "r"(b[1]));
}

// ---------- prep: x -> tf32, k-pair-interleave; per-token row sums ----------
// within each 8-block: original j stored at (j&3)*2 + (j>>2) -> (k,k+4) adjacent
__global__ void __launch_bounds__(256) prep_kernel(const float* __restrict__ x) {
    const int row = blockIdx.x;
    const int t = threadIdx.x;
    const float* xr = x + row * INF;
    float s = 0.f;
    #pragma unroll
    for (int i = 0; i < INF / 256; ++i) {
        const int k = t + i * 256;
        const float v = xr[k];
        s += v;
        const int j = k & 7;
        const int pos = (k & ~7) + ((j & 3) * 2 + (j >> 2));
        g_xtf[row * INF + pos] = __uint_as_float(f2tf(v));
    }
    #pragma unroll
    for (int off = 16; off; off >>= 1) s += __shfl_xor_sync(0xffffffffu, s, off);
    __shared__ float red[8];
    if ((t & 31) == 0) red[t >> 5] = s;
    __syncthreads();
    if (t < 8) {
        float v = red[t];
        #pragma unroll
        for (int off = 4; off; off >>= 1) v += __shfl_xor_sync(0xffu, v, off);
        if (t == 0) g_xsum[row] = v;
    }
}

// ---------- main GEMM ----------
__global__ void __launch_bounds__(512, 1)
qbits_kernel(const int* __restrict__ W, const float* __restrict__ scales,
             const float* __restrict__ u, const float* __restrict__ bias,
             float* __restrict__ out)
{
    extern __shared__ uint32_t smem[];
    const uint32_t sbase = smem_u32(smem);
    const int tid  = threadIdx.x;
    const int lane = tid & 31;
    const int warp = tid >> 5;          // 0..15
    const int wm   = warp >> 3;         // 0..1  (M: 32 rows each)
    const int wn   = warp & 7;          // 0..7  (N: 16 cols each)
    const int obase = blockIdx.x * NTILE;

    // ---- copy geometry (512 threads) ----
    // W: warp w copies k-rows {w + 16p}, p=0..3; lanes cover 128 cols (16B each)
    const int* wsrc = W + obase + (lane << 2);
    const uint32_t wdst_off = (uint32_t)((warp * WSTR + (lane << 2)) * 4);
    // x: thread t copies row t>>3, cols (t&7)*8 .. +7 (2 x 16B)
    const float* xsrc = g_xtf + (tid >> 3) * INF + ((tid & 7) << 3);
    const uint32_t xdst_off = (uint32_t)(W_STAGE_BYTES +
                              (((tid >> 3) * XSTR + ((tid & 7) << 3)) * 4));

    float acc[2][2][4];   // [mt][nt][frag]
    float accg[2][2][4];
    #pragma unroll
    for (int mt = 0; mt < 2; ++mt)
        #pragma unroll
        for (int nt = 0; nt < 2; ++nt)
            #pragma unroll
            for (int j = 0; j < 4; ++j) { acc[mt][nt][j] = 0.f; accg[mt][nt][j] = 0.f; }

    auto issue = [&](int c, int s) {
        const int k0 = c * KC;
        const uint32_t wb = sbase + (uint32_t)(s * STAGE_BYTES);
        #pragma unroll
        for (int p = 0; p < 4; ++p)
            cpasync16(wb + wdst_off + (uint32_t)(p * 16 * WSTR * 4),
                      wsrc + (k0 + warp + 16 * p) * OUTF);
        #pragma unroll
        for (int i = 0; i < 2; ++i)
            cpasync16(wb + xdst_off + (uint32_t)(i * 16), xsrc + k0 + i * 4);
        asm volatile("cp.async.commit_group;" ::: "memory");
    };

    #pragma unroll
    for (int s = 0; s < STAGES - 1; ++s) issue(s, s);

    float2 sc2[2];        // per-D-column scales, nt = 0..1
    int st = 0;
    for (int c = 0; c < NCHUNK; ++c) {
        asm volatile("cp.async.wait_group %0;" :: "n"(STAGES - 2) : "memory");
        __syncthreads();
        if (c + STAGES - 1 < NCHUNK) {
            int sn = st + STAGES - 1; if (sn >= STAGES) sn -= STAGES;
            issue(c + STAGES - 1, sn);
        }

        if ((c & 1) == 0) {
            const float* srow = scales + (c >> 1) * OUTF + obase
                              + wn * 16 + 2 * (lane & 3);
            #pragma unroll
            for (int nt = 0; nt < 2; ++nt)
                sc2[nt] = __ldg((const float2*)(srow + nt * 8));
        }

        const uint32_t* ws  = smem + st * STAGE_WORDS;
        const float*    xsm = (const float*)(ws + W_STAGE_WORDS);

        #pragma unroll
        for (int ks = 0; ks < 8; ++ks) {
            const int kp = ks * 8 + 2 * (lane & 3);   // interleaved pair offset
            const int kk = ks * 8 + (lane & 3);
            uint32_t a[2][4];
            #pragma unroll
            for (int mt = 0; mt < 2; ++mt) {
                const int r = wm * 32 + mt * 16 + (lane >> 2);
                const float2 p0 = *(const float2*)(xsm + r * XSTR + kp);        // (a0,a2)
                const float2 p1 = *(const float2*)(xsm + (r + 8) * XSTR + kp);  // (a1,a3)
                a[mt][0] = __float_as_uint(p0.x);
                a[mt][1] = __float_as_uint(p1.x);
                a[mt][2] = __float_as_uint(p0.y);
                a[mt][3] = __float_as_uint(p1.y);
            }
            #pragma unroll
            for (int nt = 0; nt < 2; ++nt) {
                const int col = wn * 16 + nt * 8 + (lane >> 2);
                const int w0 = (int)ws[kk * WSTR + col];
                const int w1 = (int)ws[(kk + 4) * WSTR + col];
                uint32_t bb[2];
                bb[0] = __float_as_uint((float)w0);   // exact in tf32
                bb[1] = __float_as_uint((float)w1);
                mma8(accg[0][nt], a[0], bb);
                mma8(accg[1][nt], a[1], bb);
            }
        }

        if (c & 1) {          // group end: fold per-D-column scale, reset raw acc
            #pragma unroll
            for (int mt = 0; mt < 2; ++mt)
                #pragma unroll
                for (int nt = 0; nt < 2; ++nt) {
                    acc[mt][nt][0] = fmaf(sc2[nt].x, accg[mt][nt][0], acc[mt][nt][0]);
                    acc[mt][nt][1] = fmaf(sc2[nt].y, accg[mt][nt][1], acc[mt][nt][1]);
                    acc[mt][nt][2] = fmaf(sc2[nt].x, accg[mt][nt][2], acc[mt][nt][2]);
                    acc[mt][nt][3] = fmaf(sc2[nt].y, accg[mt][nt][3], acc[mt][nt][3]);
                    accg[mt][nt][0] = 0.f; accg[mt][nt][1] = 0.f;
                    accg[mt][nt][2] = 0.f; accg[mt][nt][3] = 0.f;
                }
        }
        if (++st == STAGES) st = 0;
    }

    // ---- epilogue: out = acc + bias + xsum*u ----
    #pragma unroll
    for (int mt = 0; mt < 2; ++mt) {
        #pragma unroll
        for (int jr = 0; jr < 2; ++jr) {
            const int row = wm * 32 + mt * 16 + (lane >> 2) + jr * 8;
            const float xsv = g_xsum[row];
            #pragma unroll
            for (int nt = 0; nt < 2; ++nt) {
                const int col = obase + wn * 16 + nt * 8 + 2 * (lane & 3);
                const float2 bv = *(const float2*)(bias + col);
                const float2 uv = *(const float2*)(u + col);
                float2 o2;
                o2.x = acc[mt][nt][jr * 2 + 0] + bv.x + xsv * uv.x;
                o2.y = acc[mt][nt][jr * 2 + 1] + bv.y + xsv * uv.y;
                *(float2*)(out + row * OUTF + col) = o2;
            }
        }
    }
}

extern "C" void kernel_launch(void* const* d_in, const int* in_sizes, int n_in,
                              void* d_out, int out_size) {
    const float* x  = (const float*)d_in[0];
    const int*   W  = (const int*)d_in[1];
    const float* sc = (const float*)d_in[2];
    const float* u  = (const float*)d_in[3];
    const float* b  = (const float*)d_in[4];
    float* out = (float*)d_out;

    cudaFuncSetAttribute(qbits_kernel, cudaFuncAttributeMaxDynamicSharedMemorySize,
                         SMEM_BYTES);
    prep_kernel<<<TOKS, 256>>>(x);
    qbits_kernel<<<NCTA, 512, SMEM_BYTES>>>(W, sc, u, b, out);
}

// round 13
// speedup vs baseline: 1.3136x; 1.1475x over previous
#include <cuda_runtime.h>
#include <cstdint>

// out[64,14336] = x[64,4096] @ dequant(W_int) + bias + x.sum(-1)*u
// tf32 mma.sync; split-K=4 (448 CTAs, dynamic balance over 148 SMs);
// 2-stage cp.async ring, 104KB smem -> 2 CTAs resident per SM;
// W raw int32 in smem -> I2F (exact in tf32); per-group scale folding on
// D-fragment columns; deterministic gmem partials + reduce kernel.

#define TOKS   64
#define INF    4096
#define OUTF   14336
#define KC     64
#define NTILE  128
#define NTILES (OUTF / NTILE)   // 112
#define SPLITK 4
#define KPER   (INF / SPLITK)   // 1024
#define NCHUNK (KPER / KC)      // 16
#define NCTA   (NTILES * SPLITK) // 448
#define STAGES 2

// smem strides (words): W stride % 32 == 8 -> 136 ; x stride % 32 == 8 -> 72
#define WSTR 136
#define XSTR 72
#define W_STAGE_WORDS (KC * WSTR)            // 8704
#define X_STAGE_WORDS (TOKS * XSTR)          // 4608
#define STAGE_WORDS   (W_STAGE_WORDS + X_STAGE_WORDS)   // 13312
#define STAGE_BYTES   (STAGE_WORDS * 4)                 // 53248
#define W_STAGE_BYTES (W_STAGE_WORDS * 4)               // 34816
#define SMEM_BYTES    (STAGES * STAGE_BYTES)            // 106496

__device__ float g_xtf[TOKS * INF];            // tf32-rounded x, k-pair-interleaved
__device__ float g_xsum[TOKS];
__device__ float g_part[SPLITK * TOKS * OUTF]; // split-K partials (14.7MB)

static __device__ __forceinline__ uint32_t f2tf(float f) {
    uint32_t r;
    asm("cvt.rna.tf32.f32 %0, %1;" : "=r"(r) : "f"(f));
    return r;
}
static __device__ __forceinline__ uint32_t smem_u32(const void* p) {
    uint32_t a;
    asm("{ .reg .u64 t; cvta.to.shared.u64 t, %1; cvt.u32.u64 %0, t; }" : "=r"(a) : "l"(p));
    return a;
}
static __device__ __forceinline__ void cpasync16(uint32_t dst, const void* src) {
    asm volatile("cp.async.cg.shared.global [%0], [%1], 16;" :: "r"(dst), "l"(src));
}
static __device__ __forceinline__ void mma8(float* d, const uint32_t* a, const uint32_t* b) {
    asm volatile(
        "mma.sync.aligned.m16n8k8.row.col.f32.tf32.tf32.f32 "
        "{%0,%1,%2,%3}, {%4,%5,%6,%7}, {%8,%9}, {%0,%1,%2,%3};"
        : "+f"(d[0]), "+f"(d[1]), "+f"(d[2]), "+f"(d[3])
        : "r"(a[0]), "r"(a[1]), "r"(a[2]), "r"(a[3]), "r"(b[0]), "r"(b[1]));
}

// ---------- prep: x -> tf32, k-pair-interleave; per-token row sums ----------
// within each 8-block: original j stored at (j&3)*2 + (j>>2) -> (k,k+4) adjacent
__global__ void __launch_bounds__(256) prep_kernel(const float* __restrict__ x) {
    const int row = blockIdx.x;
    const int t = threadIdx.x;
    const float* xr = x + row * INF;
    float s = 0.f;
    #pragma unroll
    for (int i = 0; i < INF / 256; ++i) {
        const int k = t + i * 256;
        const float v = xr[k];
        s += v;
        const int j = k & 7;
        const int pos = (k & ~7) + ((j & 3) * 2 + (j >> 2));
        g_xtf[row * INF + pos] = __uint_as_float(f2tf(v));
    }
    #pragma unroll
    for (int off = 16; off; off >>= 1) s += __shfl_xor_sync(0xffffffffu, s, off);
    __shared__ float red[8];
    if ((t & 31) == 0) red[t >> 5] = s;
    __syncthreads();
    if (t < 8) {
        float v = red[t];
        #pragma unroll
        for (int off = 4; off; off >>= 1) v += __shfl_xor_sync(0xffu, v, off);
        if (t == 0) g_xsum[row] = v;
    }
}

// ---------- main GEMM (one split-K work unit per CTA) ----------
__global__ void __launch_bounds__(256, 2)
qbits_kernel(const int* __restrict__ W, const float* __restrict__ scales)
{
    extern __shared__ uint32_t smem[];
    const uint32_t sbase = smem_u32(smem);
    const int tid  = threadIdx.x;
    const int lane = tid & 31;
    const int warp = tid >> 5;          // 0..7
    const int wm   = warp >> 2;         // 0..1  (M: 32 rows)
    const int wn   = warp & 3;          // 0..3  (N: 32 cols)
    const int tile  = blockIdx.x % NTILES;
    const int split = blockIdx.x / NTILES;
    const int obase = tile * NTILE;
    const int kbase = split * KPER;

    // copy geometry (256 threads)
    const int*   wsrc = W + obase + (lane << 2);
    const float* xsrc = g_xtf + (tid >> 2) * INF + ((tid & 3) << 4);
    const uint32_t wdst_off = (uint32_t)((warp * WSTR + (lane << 2)) * 4);
    const uint32_t xdst_off = (uint32_t)(W_STAGE_BYTES +
                              (((tid >> 2) * XSTR + ((tid & 3) << 4)) * 4));

    float acc[2][4][4];   // scaled accumulators
    float accg[2][4][4];  // per-group raw accumulators
    #pragma unroll
    for (int mt = 0; mt < 2; ++mt)
        #pragma unroll
        for (int nt = 0; nt < 4; ++nt)
            #pragma unroll
            for (int j = 0; j < 4; ++j) { acc[mt][nt][j] = 0.f; accg[mt][nt][j] = 0.f; }

    auto issue = [&](int c, int s) {
        const int k0 = kbase + c * KC;
        const uint32_t wb = sbase + (uint32_t)(s * STAGE_BYTES);
        #pragma unroll
        for (int p = 0; p < 8; ++p)
            cpasync16(wb + wdst_off + (uint32_t)(p * 8 * WSTR * 4),
                      wsrc + (k0 + warp + 8 * p) * OUTF);
        #pragma unroll
        for (int i = 0; i < 4; ++i)
            cpasync16(wb + xdst_off + (uint32_t)(i * 16), xsrc + k0 + i * 4);
        asm volatile("cp.async.commit_group;" ::: "memory");
    };

    issue(0, 0);

    float2 sc2[4];        // per-D-column scales
    int st = 0;
    for (int c = 0; c < NCHUNK; ++c) {
        asm volatile("cp.async.wait_group 0;" ::: "memory");
        __syncthreads();
        if (c + 1 < NCHUNK) issue(c + 1, st ^ 1);

        if ((c & 1) == 0) {   // group start: fetch D-column scales
            const int g = split * (KPER / 128) + (c >> 1);
            const float* srow = scales + g * OUTF + obase + wn * 32 + 2 * (lane & 3);
            #pragma unroll
            for (int nt = 0; nt < 4; ++nt)
                sc2[nt] = __ldg((const float2*)(srow + nt * 8));
        }

        const uint32_t* ws  = smem + st * STAGE_WORDS;
        const float*    xsm = (const float*)(ws + W_STAGE_WORDS);

        #pragma unroll
        for (int ks = 0; ks < 8; ++ks) {
            const int kp = ks * 8 + 2 * (lane & 3);   // interleaved pair offset
            const int kk = ks * 8 + (lane & 3);
            uint32_t a[2][4];
            #pragma unroll
            for (int mt = 0; mt < 2; ++mt) {
                const int r = wm * 32 + mt * 16 + (lane >> 2);
                const float2 p0 = *(const float2*)(xsm + r * XSTR + kp);        // (a0,a2)
                const float2 p1 = *(const float2*)(xsm + (r + 8) * XSTR + kp);  // (a1,a3)
                a[mt][0] = __float_as_uint(p0.x);
                a[mt][1] = __float_as_uint(p1.x);
                a[mt][2] = __float_as_uint(p0.y);
                a[mt][3] = __float_as_uint(p1.y);
            }
            #pragma unroll
            for (int nt = 0; nt < 4; ++nt) {
                const int col = wn * 32 + nt * 8 + (lane >> 2);
                const int w0 = (int)ws[kk * WSTR + col];
                const int w1 = (int)ws[(kk + 4) * WSTR + col];
                uint32_t bb[2];
                bb[0] = __float_as_uint((float)w0);   // exact in tf32
                bb[1] = __float_as_uint((float)w1);
                mma8(accg[0][nt], a[0], bb);
                mma8(accg[1][nt], a[1], bb);
            }
        }

        if (c & 1) {          // group end: fold per-D-column scale, reset raw acc
            #pragma unroll
            for (int mt = 0; mt < 2; ++mt)
                #pragma unroll
                for (int nt = 0; nt < 4; ++nt) {
                    acc[mt][nt][0] = fmaf(sc2[nt].x, accg[mt][nt][0], acc[mt][nt][0]);
                    acc[mt][nt][1] = fmaf(sc2[nt].y, accg[mt][nt][1], acc[mt][nt][1]);
                    acc[mt][nt][2] = fmaf(sc2[nt].x, accg[mt][nt][2], acc[mt][nt][2]);
                    acc[mt][nt][3] = fmaf(sc2[nt].y, accg[mt][nt][3], acc[mt][nt][3]);
                    accg[mt][nt][0] = 0.f; accg[mt][nt][1] = 0.f;
                    accg[mt][nt][2] = 0.f; accg[mt][nt][3] = 0.f;
                }
        }
        st ^= 1;
    }

    // ---- epilogue: write partial tile (no bias/u — reduce kernel adds) ----
    float* part = g_part + split * (TOKS * OUTF);
    #pragma unroll
    for (int mt = 0; mt < 2; ++mt) {
        #pragma unroll
        for (int jr = 0; jr < 2; ++jr) {
            const int row = wm * 32 + mt * 16 + (lane >> 2) + jr * 8;
            #pragma unroll
            for (int nt = 0; nt < 4; ++nt) {
                const int col = obase + wn * 32 + nt * 8 + 2 * (lane & 3);
                float2 o2;
                o2.x = acc[mt][nt][jr * 2 + 0];
                o2.y = acc[mt][nt][jr * 2 + 1];
                *(float2*)(part + row * OUTF + col) = o2;
            }
        }
    }
}

// ---------- reduce: out = sum(partials) + bias + xsum*u ----------
__global__ void __launch_bounds__(256)
reduce_kernel(const float* __restrict__ u, const float* __restrict__ bias,
              float* __restrict__ out)
{
    const int idx = blockIdx.x * 256 + threadIdx.x;       // over float4 units
    const int t   = idx / (OUTF / 4);
    const int c4  = (idx % (OUTF / 4)) * 4;
    const float xs = g_xsum[t];
    const int base = t * OUTF + c4;
    float4 s0 = *(const float4*)(g_part + 0 * TOKS * OUTF + base);
    float4 s1 = *(const float4*)(g_part + 1 * TOKS * OUTF + base);
    float4 s2 = *(const float4*)(g_part + 2 * TOKS * OUTF + base);
    float4 s3 = *(const float4*)(g_part + 3 * TOKS * OUTF + base);
    const float4 bv = *(const float4*)(bias + c4);
    const float4 uv = *(const float4*)(u + c4);
    float4 r;
    r.x = (s0.x + s1.x) + (s2.x + s3.x) + bv.x + xs * uv.x;
    r.y = (s0.y + s1.y) + (s2.y + s3.y) + bv.y + xs * uv.y;
    r.z = (s0.z + s1.z) + (s2.z + s3.z) + bv.z + xs * uv.z;
    r.w = (s0.w + s1.w) + (s2.w + s3.w) + bv.w + xs * uv.w;
    *(float4*)(out + base) = r;
}

extern "C" void kernel_launch(void* const* d_in, const int* in_sizes, int n_in,
                              void* d_out, int out_size) {
    const float* x  = (const float*)d_in[0];
    const int*   W  = (const int*)d_in[1];
    const float* sc = (const float*)d_in[2];
    const float* u  = (const float*)d_in[3];
    const float* b  = (const float*)d_in[4];
    float* out = (float*)d_out;

    cudaFuncSetAttribute(qbits_kernel, cudaFuncAttributeMaxDynamicSharedMemorySize,
                         SMEM_BYTES);
    prep_kernel<<<TOKS, 256>>>(x);
    qbits_kernel<<<NCTA, 256, SMEM_BYTES>>>(W, sc);
    reduce_kernel<<<(TOKS * OUTF / 4) / 256, 256>>>(u, b, out);
}